// round 2
// baseline (speedup 1.0000x reference)
#include <cuda_runtime.h>
#include <math.h>

#define HIDDEN 256
#define HS     512
#define NHEADS 8
#define HDIM   64
#define NN     8        // tokens
#define NB     8        // batch
#define HH     32
#define WW     32
#define NPIX   (NB*HH*WW)   // 8192
#define EPSV   1e-6f

// scratch (static __device__ — no allocation allowed)
__device__ float g_kq[NB*NHEADS*HIDDEN];             // [b][e][c], attn_scale folded in
__device__ float g_cbar[(size_t)NPIX*NHEADS*HIDDEN]; // [px][e][c]  64MB

// ---------------------------------------------------------------------------
// Kernel 0: query path. emb lookup -> silu MLP -> qh -> kq[b,e,c] = scale * Wk_e^T qh_e
// grid = 8 (one block per batch), 256 threads
// ---------------------------------------------------------------------------
__global__ void qpath_kernel(const int* __restrict__ q,
                             const float* __restrict__ emb,
                             const float* __restrict__ w1, const float* __restrict__ b1,
                             const float* __restrict__ w2, const float* __restrict__ b2,
                             const float* __restrict__ w_kv)
{
    __shared__ float qe[HIDDEN];
    __shared__ float h1[HS];
    __shared__ float qh[HS];
    int b = blockIdx.x, t = threadIdx.x;
    int row = q[b];
    qe[t] = emb[(size_t)row*HIDDEN + t];
    __syncthreads();

    for (int j = t; j < HS; j += 256) {
        float acc = b1[j];
        #pragma unroll 8
        for (int c = 0; c < HIDDEN; c++) acc += qe[c]*w1[(size_t)c*HS + j];
        h1[j] = acc / (1.f + expf(-acc));   // silu
    }
    __syncthreads();
    for (int j = t; j < HS; j += 256) {
        float acc = b2[j];
        #pragma unroll 8
        for (int i = 0; i < HS; i++) acc += h1[i]*w2[(size_t)i*HS + j];
        qh[j] = acc;
    }
    __syncthreads();
    const float scale = rsqrtf((float)HDIM);
    for (int o = t; o < NHEADS*HIDDEN; o += 256) {
        int e = o >> 8, c = o & 255;
        float acc = 0.f;
        #pragma unroll 8
        for (int d = 0; d < HDIM; d++)
            acc += qh[e*HDIM + d] * w_kv[(size_t)c*(2*HS) + e*128 + d];  // K half of head e
        g_kq[b*NHEADS*HIDDEN + o] = acc * scale;
    }
}

// ---------------------------------------------------------------------------
// Kernel A: per-pixel RMSNorm + dots + softmax + cbar
// block = 4 pixels (fixed b,h, w0..w0+3), 256 threads, grid = 8*32*8 = 2048
// ---------------------------------------------------------------------------
#define APX 4
__global__ void attn_kernel(const float* __restrict__ c, const float* __restrict__ rms_w)
{
    __shared__ float cn[NN*APX*HIDDEN];      // [(n*4+w)*256+ch]  32KB
    __shared__ float kq_s[NHEADS*HIDDEN];    // 8KB
    __shared__ float rstd_s[NN*APX];
    __shared__ float rw_s[HIDDEN];
    __shared__ float dots_s[APX*NHEADS*NN];
    __shared__ float attn_s[APX*NHEADS*NN];

    int t = threadIdx.x;
    int blk = blockIdx.x;
    int b  = blk >> 8;
    int h  = (blk >> 3) & 31;
    int w0 = (blk & 7) * APX;

    for (int i = t; i < NHEADS*HIDDEN; i += 256) kq_s[i] = g_kq[b*NHEADS*HIDDEN + i];
    if (t < HIDDEN) rw_s[t] = rms_w[t];

    // load c tile: c[b, n, ch, h, w0+wl]
    const float* cb = c + ((size_t)b*NN)*HIDDEN*(HH*WW) + h*WW + w0;
    int wl = t & 3, chb = t >> 2;            // 64 ch per pass
    for (int n = 0; n < NN; n++) {
        #pragma unroll
        for (int cp = 0; cp < 4; cp++) {
            int ch = cp*64 + chb;
            cn[(n*APX + wl)*HIDDEN + ch] = cb[((size_t)n*HIDDEN + ch)*(HH*WW) + wl];
        }
    }
    __syncthreads();

    // sumsq per (n,w): 32 pairs x 8 threads
    {
        int pair = t >> 3, sub = t & 7;
        float ss = 0.f;
        for (int ch = sub; ch < HIDDEN; ch += 8) {
            float v = cn[pair*HIDDEN + ch]; ss += v*v;
        }
        ss += __shfl_xor_sync(0xffffffff, ss, 4);
        ss += __shfl_xor_sync(0xffffffff, ss, 2);
        ss += __shfl_xor_sync(0xffffffff, ss, 1);
        if (sub == 0) rstd_s[pair] = rsqrtf(ss*(1.f/HIDDEN) + EPSV);
    }
    __syncthreads();

    // normalize in place (rms_w applied)
    for (int i = t; i < NN*APX*HIDDEN; i += 256) {
        int pr = i >> 8, ch = i & 255;
        cn[i] *= rstd_s[pr] * rw_s[ch];
    }
    __syncthreads();

    // dots: one per thread. t -> (w,e,n)
    {
        int dw = t >> 6, de = (t >> 3) & 7, dn = t & 7;
        int lane = t & 31;
        const float* crow = &cn[(dn*APX + dw)*HIDDEN];
        const float* krow = &kq_s[de*HIDDEN];
        float acc = 0.f;
        #pragma unroll 8
        for (int i = 0; i < HIDDEN; i++) {
            int ch = (i + lane) & 255;       // skew to avoid bank conflicts
            acc += crow[ch]*krow[ch];
        }
        dots_s[(dw*NHEADS + de)*NN + dn] = acc;
    }
    __syncthreads();

    // softmax over n: 32 (w,e) groups
    if (t < APX*NHEADS) {
        float m = -1e30f;
        #pragma unroll
        for (int n = 0; n < NN; n++) m = fmaxf(m, dots_s[t*NN + n]);
        float ex[NN]; float s = 0.f;
        #pragma unroll
        for (int n = 0; n < NN; n++) { ex[n] = expf(dots_s[t*NN + n] - m); s += ex[n]; }
        float inv = 1.f/s;
        #pragma unroll
        for (int n = 0; n < NN; n++) attn_s[t*NN + n] = ex[n]*inv;
    }
    __syncthreads();

    // cbar[w,e,ch] -> global
    int px_base = b*(HH*WW) + h*WW + w0;
    for (int p = 0; p < APX*NHEADS; p++) {
        int w = p >> 3, e = p & 7;
        float acc = 0.f;
        #pragma unroll
        for (int n = 0; n < NN; n++)
            acc += attn_s[p*NN + n] * cn[(n*APX + w)*HIDDEN + t];
        g_cbar[(size_t)(px_base + w)*(NHEADS*HIDDEN) + e*HIDDEN + t] = acc;
    }
}

// ---------------------------------------------------------------------------
// Kernel B: per 64-pixel tile: for each head  h_e = cbar_e @ Wv_e   (64x256 * 256x64)
// then out += h_e @ Wo_e (64x64 * 64x256), bias + transposed store.
// 256 threads, 48KB static smem (no padding: all smem reads are broadcast or
// stride-1 in tx, so padding buys nothing), grid = 128
// ---------------------------------------------------------------------------
#define BPX 64

__global__ __launch_bounds__(256, 1)
void out_kernel(const float* __restrict__ w_kv, const float* __restrict__ w_out,
                const float* __restrict__ b_out, float* __restrict__ out)
{
    __shared__ float sm[12288];  // 49152 bytes (static limit)
    float* a_s  = sm;            // [64][64]  cbar K-chunk
    float* wv_s = sm + 4096;     // [64][64]  Wv K-chunk
    float* wo_s = sm;            // [64][128] aliases a_s+wv_s exactly (8192 floats)
    float* h_s  = sm + 8192;     // [64][64]

    int t  = threadIdx.x;
    int ty = t >> 4, tx = t & 15;      // 16x16 thread grid
    int p0 = blockIdx.x * BPX;

    float oacc[4][16];
    #pragma unroll
    for (int i = 0; i < 4; i++)
        #pragma unroll
        for (int s = 0; s < 16; s++) oacc[i][s] = 0.f;

    for (int e = 0; e < NHEADS; e++) {
        // ---- GEMM1: h[64px, 64d] = cbar[64,256] @ Wv_e[256,64], K chunked by 64 ----
        float c1[16];
        #pragma unroll
        for (int i = 0; i < 16; i++) c1[i] = 0.f;

        for (int kc = 0; kc < 4; kc++) {
            for (int i = t; i < 4096; i += 256) {
                int px = i >> 6, k = i & 63;
                a_s[px*64 + k] = g_cbar[(size_t)(p0 + px)*(NHEADS*HIDDEN) + e*HIDDEN + kc*64 + k];
            }
            for (int i = t; i < 4096; i += 256) {
                int k = i >> 6, d = i & 63;
                wv_s[k*64 + d] = w_kv[(size_t)(kc*64 + k)*(2*HS) + e*128 + 64 + d];  // V half
            }
            __syncthreads();
            #pragma unroll 8
            for (int k = 0; k < 64; k++) {
                float a0 = a_s[(ty*4+0)*64 + k];
                float a1 = a_s[(ty*4+1)*64 + k];
                float a2 = a_s[(ty*4+2)*64 + k];
                float a3 = a_s[(ty*4+3)*64 + k];
                #pragma unroll
                for (int jj = 0; jj < 4; jj++) {
                    float bb = wv_s[k*64 + tx + jj*16];
                    c1[0*4+jj] += a0*bb;
                    c1[1*4+jj] += a1*bb;
                    c1[2*4+jj] += a2*bb;
                    c1[3*4+jj] += a3*bb;
                }
            }
            __syncthreads();
        }
        // write h tile to smem (d index = tx + jj*16)
        #pragma unroll
        for (int i = 0; i < 4; i++)
            #pragma unroll
            for (int jj = 0; jj < 4; jj++)
                h_s[(ty*4+i)*64 + tx + jj*16] = c1[i*4+jj];
        __syncthreads();

        // ---- GEMM2: out[64,256] += h[64,64] @ Wo_e[64,256], N chunked by 128 ----
        for (int cc = 0; cc < 2; cc++) {
            for (int i = t; i < 8192; i += 256) {
                int j = i >> 7, ch = i & 127;
                wo_s[j*128 + ch] = w_out[(size_t)(e*64 + j)*HIDDEN + cc*128 + ch];
            }
            __syncthreads();
            #pragma unroll 4
            for (int j = 0; j < 64; j++) {
                float h0 = h_s[(ty*4+0)*64 + j];
                float h1 = h_s[(ty*4+1)*64 + j];
                float h2 = h_s[(ty*4+2)*64 + j];
                float h3 = h_s[(ty*4+3)*64 + j];
                #pragma unroll
                for (int k8 = 0; k8 < 8; k8++) {
                    float wv = wo_s[j*128 + tx + k8*16];
                    int s = cc*8 + k8;
                    oacc[0][s] += h0*wv;
                    oacc[1][s] += h1*wv;
                    oacc[2][s] += h2*wv;
                    oacc[3][s] += h3*wv;
                }
            }
            __syncthreads();
        }
    }

    // bias + transposed store: out[b, ch, h, w]
    #pragma unroll
    for (int i = 0; i < 4; i++) {
        int px = p0 + ty*4 + i;
        int bb = px >> 10, hh = (px >> 5) & 31, ww = px & 31;
        #pragma unroll
        for (int s = 0; s < 16; s++) {
            int ch = (s >> 3)*128 + (s & 7)*16 + tx;
            out[(((size_t)bb*HIDDEN + ch)*HH + hh)*WW + ww] = oacc[i][s] + b_out[ch];
        }
    }
}

// ---------------------------------------------------------------------------
extern "C" void kernel_launch(void* const* d_in, const int* in_sizes, int n_in,
                              void* d_out, int out_size)
{
    const int*   q     = (const int*)  d_in[0];
    const float* c     = (const float*)d_in[1];
    const float* rms_w = (const float*)d_in[2];
    const float* emb   = (const float*)d_in[3];
    const float* w1    = (const float*)d_in[4];
    const float* b1    = (const float*)d_in[5];
    const float* w2    = (const float*)d_in[6];
    const float* b2    = (const float*)d_in[7];
    const float* w_kv  = (const float*)d_in[8];
    const float* w_out = (const float*)d_in[9];
    const float* b_out = (const float*)d_in[10];
    float* out = (float*)d_out;

    qpath_kernel<<<NB, 256>>>(q, emb, w1, b1, w2, b2, w_kv);
    attn_kernel<<<2048, 256>>>(c, rms_w);
    out_kernel<<<NPIX/BPX, 256>>>(w_kv, w_out, b_out, out);
}

// round 3
// speedup vs baseline: 1.2563x; 1.2563x over previous
#include <cuda_runtime.h>
#include <math.h>

#define HIDDEN 256
#define HS     512
#define NHEADS 8
#define HDIM   64
#define NN     8        // tokens
#define NB     8        // batch
#define HH     32
#define WW     32
#define NPIX   (NB*HH*WW)   // 8192
#define EPSV   1e-6f

// scratch (static __device__ — no allocation allowed)
__device__ float g_h1[NB*HS];
__device__ float g_qh[NB*HS];
__device__ float g_kq[NB*NHEADS*HIDDEN];             // [b][e][c], attn_scale folded in
__device__ float g_cbar[(size_t)NPIX*NHEADS*HIDDEN]; // [px][e][c]  64MB

// ---------------------------------------------------------------------------
// Query path, stage 1: h1[b,j] = silu(emb[q[b]] @ w1 + b1)
// grid = 16 (j-chunks of 32), block = 256 = (8 b x 32 j)
// ---------------------------------------------------------------------------
__global__ void q1_kernel(const int* __restrict__ q, const float* __restrict__ emb,
                          const float* __restrict__ w1, const float* __restrict__ b1)
{
    __shared__ float qe[NB][HIDDEN];
    int t = threadIdx.x;
    for (int i = t; i < NB*HIDDEN; i += 256) {
        int b = i >> 8, cc = i & 255;
        qe[b][cc] = emb[(size_t)q[b]*HIDDEN + cc];
    }
    __syncthreads();
    int b = t >> 5, jl = t & 31;
    int j = blockIdx.x*32 + jl;
    float acc = b1[j];
    #pragma unroll 8
    for (int cc = 0; cc < HIDDEN; cc++) acc += qe[b][cc] * w1[(size_t)cc*HS + j];
    g_h1[b*HS + j] = acc / (1.f + expf(-acc));
}

// ---------------------------------------------------------------------------
// Query path, stage 2: qh[b,j] = h1[b] @ w2 + b2
// grid = 16, block = 256 = (8 b x 32 j)
// ---------------------------------------------------------------------------
__global__ void q2_kernel(const float* __restrict__ w2, const float* __restrict__ b2)
{
    __shared__ float h1s[NB][HS];
    int t = threadIdx.x;
    for (int i = t; i < NB*HS; i += 256) h1s[i >> 9][i & 511] = g_h1[i];
    __syncthreads();
    int b = t >> 5, jl = t & 31;
    int j = blockIdx.x*32 + jl;
    float acc = b2[j];
    #pragma unroll 8
    for (int i = 0; i < HS; i++) acc += h1s[b][i] * w2[(size_t)i*HS + j];
    g_qh[b*HS + j] = acc;
}

// ---------------------------------------------------------------------------
// Query path, stage 3: kq[b,e,c] = scale * (Wk_e^T qh_e)[c]
// grid = 64 = (b,e), block = 256 (c). Each thread streams 64 contiguous w_kv
// floats (float4 x16).
// ---------------------------------------------------------------------------
__global__ void q3_kernel(const float* __restrict__ w_kv)
{
    int b = blockIdx.x >> 3, e = blockIdx.x & 7;
    __shared__ float qhe[HDIM];
    int t = threadIdx.x;
    if (t < HDIM) qhe[t] = g_qh[b*HS + e*HDIM + t];
    __syncthreads();
    const float scale = rsqrtf((float)HDIM);
    const float4* wp = (const float4*)(w_kv + (size_t)t*(2*HS) + e*128);  // K half
    float acc = 0.f;
    #pragma unroll
    for (int d4 = 0; d4 < 16; d4++) {
        float4 v = wp[d4];
        acc += v.x*qhe[d4*4+0] + v.y*qhe[d4*4+1] + v.z*qhe[d4*4+2] + v.w*qhe[d4*4+3];
    }
    g_kq[b*NHEADS*HIDDEN + e*HIDDEN + t] = acc * scale;
}

// ---------------------------------------------------------------------------
// Kernel A: per-pixel RMSNorm + dots + softmax + cbar
// block = 8 pixels (fixed b,h, w0..w0+7) -> every global load covers full 32B
// sectors. 256 threads, grid = 8*32*4 = 1024. Dynamic smem ~80KB.
// cn row stride 260 floats: bank = (row*4 + ch) & 31 -> conflict-free in all
// access patterns below.
// ---------------------------------------------------------------------------
#define APX 8
#define CNS 260     // padded row stride (floats)
#define SMEM_A_FLOATS (NN*APX*CNS + NHEADS*HIDDEN + HIDDEN + NN*APX + 2*APX*NHEADS*NN)
#define SMEM_A_BYTES  (SMEM_A_FLOATS*4)

__global__ __launch_bounds__(256)
void attn_kernel(const float* __restrict__ c, const float* __restrict__ rms_w)
{
    extern __shared__ float sma[];
    float* cn     = sma;                              // [64 rows][260]
    float* kq_s   = cn + NN*APX*CNS;                  // 2048
    float* rw_s   = kq_s + NHEADS*HIDDEN;             // 256
    float* rstd_s = rw_s + HIDDEN;                    // 64
    float* dots_s = rstd_s + NN*APX;                  // 512
    float* attn_s = dots_s + APX*NHEADS*NN;           // 512

    int t = threadIdx.x;
    int blk = blockIdx.x;
    int b  = blk >> 7;
    int h  = (blk >> 2) & 31;
    int w0 = (blk & 3) * APX;

    for (int i = t; i < NHEADS*HIDDEN; i += 256) kq_s[i] = g_kq[b*NHEADS*HIDDEN + i];
    if (t < HIDDEN) rw_s[t] = rms_w[t];

    // load c tile: c[b, n, ch, h, w0+wl]; warp covers (4 ch) x (8 wl=32B sector)
    const float* cb = c + ((size_t)b*NN)*HIDDEN*(HH*WW) + h*WW + w0;
    int wl = t & 7, chb = t >> 3;            // chb 0..31
    for (int n = 0; n < NN; n++) {
        #pragma unroll
        for (int cp = 0; cp < 8; cp++) {
            int ch = cp*32 + chb;
            cn[(n*APX + wl)*CNS + ch] = cb[((size_t)n*HIDDEN + ch)*(HH*WW) + wl];
        }
    }
    __syncthreads();

    // sumsq per row: 64 rows x 4 threads
    {
        int row = t >> 2, sub = t & 3;
        float ss = 0.f;
        for (int ch = sub; ch < HIDDEN; ch += 4) {
            float v = cn[row*CNS + ch]; ss += v*v;
        }
        ss += __shfl_xor_sync(0xffffffffu, ss, 1);
        ss += __shfl_xor_sync(0xffffffffu, ss, 2);
        if (sub == 0) rstd_s[row] = rsqrtf(ss*(1.f/HIDDEN) + EPSV);
    }
    __syncthreads();

    // normalize in place (rms_w applied)
    for (int i = t; i < NN*APX*HIDDEN; i += 256) {
        int row = i >> 8, ch = i & 255;
        cn[row*CNS + ch] *= rstd_s[row] * rw_s[ch];
    }
    __syncthreads();

    // dots: thread (w,n) pair + ch-quarter; register-blocked over all 8 heads.
    {
        int p2 = t >> 2, sub = t & 3, lane = t & 31;
        int w = p2 >> 3, n = p2 & 7;
        const float* crow = &cn[(n*APX + w)*CNS];
        float pd[NHEADS];
        #pragma unroll
        for (int e = 0; e < NHEADS; e++) pd[e] = 0.f;
        #pragma unroll 4
        for (int j = 0; j < 64; j++) {
            int ch = sub*64 + ((j + lane) & 63);   // lane-skewed: conflict-free
            float cv = crow[ch];
            #pragma unroll
            for (int e = 0; e < NHEADS; e++) pd[e] += cv * kq_s[e*HIDDEN + ch];
        }
        #pragma unroll
        for (int e = 0; e < NHEADS; e++) {
            pd[e] += __shfl_xor_sync(0xffffffffu, pd[e], 1);
            pd[e] += __shfl_xor_sync(0xffffffffu, pd[e], 2);
        }
        if (sub == 0) {
            #pragma unroll
            for (int e = 0; e < NHEADS; e++) dots_s[(w*NHEADS + e)*NN + n] = pd[e];
        }
    }
    __syncthreads();

    // softmax over n: 64 (w,e) groups
    if (t < APX*NHEADS) {
        float m = -1e30f;
        #pragma unroll
        for (int n = 0; n < NN; n++) m = fmaxf(m, dots_s[t*NN + n]);
        float ex[NN]; float s = 0.f;
        #pragma unroll
        for (int n = 0; n < NN; n++) { ex[n] = expf(dots_s[t*NN + n] - m); s += ex[n]; }
        float inv = 1.f/s;
        #pragma unroll
        for (int n = 0; n < NN; n++) attn_s[t*NN + n] = ex[n]*inv;
    }
    __syncthreads();

    // cbar: per w, load 8 token values once into regs, reuse across 8 heads
    int px_base = b*(HH*WW) + h*WW + w0;
    for (int w = 0; w < APX; w++) {
        float cv[NN];
        #pragma unroll
        for (int n = 0; n < NN; n++) cv[n] = cn[(n*APX + w)*CNS + t];
        #pragma unroll
        for (int e = 0; e < NHEADS; e++) {
            float acc = 0.f;
            #pragma unroll
            for (int n = 0; n < NN; n++) acc += attn_s[(w*NHEADS + e)*NN + n] * cv[n];
            g_cbar[(size_t)(px_base + w)*(NHEADS*HIDDEN) + e*HIDDEN + t] = acc;
        }
    }
}

// ---------------------------------------------------------------------------
// Kernel B: per 64-pixel tile: for each head  h_e = cbar_e @ Wv_e  (64x256 * 256x64)
// then out += h_e @ Wo_e (64x64 * 64x256), bias + transposed store.
// 256 threads, 48KB static smem, grid = 128
// ---------------------------------------------------------------------------
#define BPX 64

__global__ __launch_bounds__(256, 1)
void out_kernel(const float* __restrict__ w_kv, const float* __restrict__ w_out,
                const float* __restrict__ b_out, float* __restrict__ out)
{
    __shared__ float sm[12288];  // 49152 bytes
    float* a_s  = sm;            // [64][64]  cbar K-chunk
    float* wv_s = sm + 4096;     // [64][64]  Wv K-chunk
    float* wo_s = sm;            // [64][128] aliases a_s+wv_s exactly
    float* h_s  = sm + 8192;     // [64][64]

    int t  = threadIdx.x;
    int ty = t >> 4, tx = t & 15;      // 16x16 thread grid
    int p0 = blockIdx.x * BPX;

    float oacc[4][16];
    #pragma unroll
    for (int i = 0; i < 4; i++)
        #pragma unroll
        for (int s = 0; s < 16; s++) oacc[i][s] = 0.f;

    for (int e = 0; e < NHEADS; e++) {
        float c1[16];
        #pragma unroll
        for (int i = 0; i < 16; i++) c1[i] = 0.f;

        for (int kc = 0; kc < 4; kc++) {
            for (int i = t; i < 4096; i += 256) {
                int px = i >> 6, k = i & 63;
                a_s[px*64 + k] = g_cbar[(size_t)(p0 + px)*(NHEADS*HIDDEN) + e*HIDDEN + kc*64 + k];
            }
            for (int i = t; i < 4096; i += 256) {
                int k = i >> 6, d = i & 63;
                wv_s[k*64 + d] = w_kv[(size_t)(kc*64 + k)*(2*HS) + e*128 + 64 + d];  // V half
            }
            __syncthreads();
            #pragma unroll 8
            for (int k = 0; k < 64; k++) {
                float a0 = a_s[(ty*4+0)*64 + k];
                float a1 = a_s[(ty*4+1)*64 + k];
                float a2 = a_s[(ty*4+2)*64 + k];
                float a3 = a_s[(ty*4+3)*64 + k];
                #pragma unroll
                for (int jj = 0; jj < 4; jj++) {
                    float bb = wv_s[k*64 + tx + jj*16];
                    c1[0*4+jj] += a0*bb;
                    c1[1*4+jj] += a1*bb;
                    c1[2*4+jj] += a2*bb;
                    c1[3*4+jj] += a3*bb;
                }
            }
            __syncthreads();
        }
        #pragma unroll
        for (int i = 0; i < 4; i++)
            #pragma unroll
            for (int jj = 0; jj < 4; jj++)
                h_s[(ty*4+i)*64 + tx + jj*16] = c1[i*4+jj];
        __syncthreads();

        for (int cc = 0; cc < 2; cc++) {
            for (int i = t; i < 8192; i += 256) {
                int j = i >> 7, ch = i & 127;
                wo_s[j*128 + ch] = w_out[(size_t)(e*64 + j)*HIDDEN + cc*128 + ch];
            }
            __syncthreads();
            #pragma unroll 4
            for (int j = 0; j < 64; j++) {
                float h0 = h_s[(ty*4+0)*64 + j];
                float h1 = h_s[(ty*4+1)*64 + j];
                float h2 = h_s[(ty*4+2)*64 + j];
                float h3 = h_s[(ty*4+3)*64 + j];
                #pragma unroll
                for (int k8 = 0; k8 < 8; k8++) {
                    float wv = wo_s[j*128 + tx + k8*16];
                    int s = cc*8 + k8;
                    oacc[0][s] += h0*wv;
                    oacc[1][s] += h1*wv;
                    oacc[2][s] += h2*wv;
                    oacc[3][s] += h3*wv;
                }
            }
            __syncthreads();
        }
    }

    // bias + transposed store: out[b, ch, h, w]
    #pragma unroll
    for (int i = 0; i < 4; i++) {
        int px = p0 + ty*4 + i;
        int bb = px >> 10, hh = (px >> 5) & 31, ww = px & 31;
        #pragma unroll
        for (int s = 0; s < 16; s++) {
            int ch = (s >> 3)*128 + (s & 7)*16 + tx;
            out[(((size_t)bb*HIDDEN + ch)*HH + hh)*WW + ww] = oacc[i][s] + b_out[ch];
        }
    }
}

// ---------------------------------------------------------------------------
extern "C" void kernel_launch(void* const* d_in, const int* in_sizes, int n_in,
                              void* d_out, int out_size)
{
    const int*   q     = (const int*)  d_in[0];
    const float* c     = (const float*)d_in[1];
    const float* rms_w = (const float*)d_in[2];
    const float* emb   = (const float*)d_in[3];
    const float* w1    = (const float*)d_in[4];
    const float* b1    = (const float*)d_in[5];
    const float* w2    = (const float*)d_in[6];
    const float* b2    = (const float*)d_in[7];
    const float* w_kv  = (const float*)d_in[8];
    const float* w_out = (const float*)d_in[9];
    const float* b_out = (const float*)d_in[10];
    float* out = (float*)d_out;

    static int smem_set = 0;
    if (!smem_set) {
        cudaFuncSetAttribute(attn_kernel, cudaFuncAttributeMaxDynamicSharedMemorySize,
                             SMEM_A_BYTES);
        smem_set = 1;
    }

    q1_kernel<<<16, 256>>>(q, emb, w1, b1);
    q2_kernel<<<16, 256>>>(w2, b2);
    q3_kernel<<<64, 256>>>(w_kv);
    attn_kernel<<<NB*HH*(WW/APX), 256, SMEM_A_BYTES>>>(c, rms_w);
    out_kernel<<<NPIX/BPX, 256>>>(w_kv, w_out, b_out, out);
}

// round 4
// speedup vs baseline: 1.5529x; 1.2361x over previous
#include <cuda_runtime.h>
#include <math.h>
#include <stdint.h>

#define HIDDEN 256
#define HS     512
#define NHEADS 8
#define HDIM   64
#define NN     8        // tokens
#define NB     8        // batch
#define HH     32
#define WW     32
#define NPIX   (NB*HH*WW)   // 8192
#define EPSV   1e-6f

// scratch (static __device__ — no allocation allowed)
__device__ float g_h1[NB*HS];
__device__ float g_qh[NB*HS];
__device__ float g_kq[NB*NHEADS*HIDDEN];             // [b][e][c], attn_scale folded in
__device__ float g_cbar[(size_t)NPIX*NHEADS*HIDDEN]; // [px][e][c]  64MB

// ---------------------------------------------------------------------------
// Query path, stage 1: h1[b,j] = silu(emb[q[b]] @ w1 + b1)
// ---------------------------------------------------------------------------
__global__ void q1_kernel(const int* __restrict__ q, const float* __restrict__ emb,
                          const float* __restrict__ w1, const float* __restrict__ b1)
{
    __shared__ float qe[NB][HIDDEN];
    int t = threadIdx.x;
    for (int i = t; i < NB*HIDDEN; i += 256) {
        int b = i >> 8, cc = i & 255;
        qe[b][cc] = emb[(size_t)q[b]*HIDDEN + cc];
    }
    __syncthreads();
    int b = t >> 5, jl = t & 31;
    int j = blockIdx.x*32 + jl;
    float acc = b1[j];
    #pragma unroll 8
    for (int cc = 0; cc < HIDDEN; cc++) acc += qe[b][cc] * w1[(size_t)cc*HS + j];
    g_h1[b*HS + j] = acc / (1.f + expf(-acc));
}

// ---------------------------------------------------------------------------
// Query path, stage 2: qh[b,j] = h1[b] @ w2 + b2
// ---------------------------------------------------------------------------
__global__ void q2_kernel(const float* __restrict__ w2, const float* __restrict__ b2)
{
    __shared__ float h1s[NB][HS];
    int t = threadIdx.x;
    for (int i = t; i < NB*HS; i += 256) h1s[i >> 9][i & 511] = g_h1[i];
    __syncthreads();
    int b = t >> 5, jl = t & 31;
    int j = blockIdx.x*32 + jl;
    float acc = b2[j];
    #pragma unroll 8
    for (int i = 0; i < HS; i++) acc += h1s[b][i] * w2[(size_t)i*HS + j];
    g_qh[b*HS + j] = acc;
}

// ---------------------------------------------------------------------------
// Query path, stage 3: kq[b,e,c] = scale * (Wk_e^T qh_e)[c]
// ---------------------------------------------------------------------------
__global__ void q3_kernel(const float* __restrict__ w_kv)
{
    int b = blockIdx.x >> 3, e = blockIdx.x & 7;
    __shared__ float qhe[HDIM];
    int t = threadIdx.x;
    if (t < HDIM) qhe[t] = g_qh[b*HS + e*HDIM + t];
    __syncthreads();
    const float scale = rsqrtf((float)HDIM);
    const float4* wp = (const float4*)(w_kv + (size_t)t*(2*HS) + e*128);  // K half
    float acc = 0.f;
    #pragma unroll
    for (int d4 = 0; d4 < 16; d4++) {
        float4 v = wp[d4];
        acc += v.x*qhe[d4*4+0] + v.y*qhe[d4*4+1] + v.z*qhe[d4*4+2] + v.w*qhe[d4*4+3];
    }
    g_kq[b*NHEADS*HIDDEN + e*HIDDEN + t] = acc * scale;
}

// ---------------------------------------------------------------------------
// Kernel A: per-pixel RMSNorm + dots + softmax + cbar (unchanged from R3)
// ---------------------------------------------------------------------------
#define APX 8
#define CNS 260
#define SMEM_A_FLOATS (NN*APX*CNS + NHEADS*HIDDEN + HIDDEN + NN*APX + 2*APX*NHEADS*NN)
#define SMEM_A_BYTES  (SMEM_A_FLOATS*4)

__global__ __launch_bounds__(256)
void attn_kernel(const float* __restrict__ c, const float* __restrict__ rms_w)
{
    extern __shared__ float sma[];
    float* cn     = sma;
    float* kq_s   = cn + NN*APX*CNS;
    float* rw_s   = kq_s + NHEADS*HIDDEN;
    float* rstd_s = rw_s + HIDDEN;
    float* dots_s = rstd_s + NN*APX;
    float* attn_s = dots_s + APX*NHEADS*NN;

    int t = threadIdx.x;
    int blk = blockIdx.x;
    int b  = blk >> 7;
    int h  = (blk >> 2) & 31;
    int w0 = (blk & 3) * APX;

    for (int i = t; i < NHEADS*HIDDEN; i += 256) kq_s[i] = g_kq[b*NHEADS*HIDDEN + i];
    if (t < HIDDEN) rw_s[t] = rms_w[t];

    const float* cb = c + ((size_t)b*NN)*HIDDEN*(HH*WW) + h*WW + w0;
    int wl = t & 7, chb = t >> 3;
    for (int n = 0; n < NN; n++) {
        #pragma unroll
        for (int cp = 0; cp < 8; cp++) {
            int ch = cp*32 + chb;
            cn[(n*APX + wl)*CNS + ch] = cb[((size_t)n*HIDDEN + ch)*(HH*WW) + wl];
        }
    }
    __syncthreads();

    {
        int row = t >> 2, sub = t & 3;
        float ss = 0.f;
        for (int ch = sub; ch < HIDDEN; ch += 4) {
            float v = cn[row*CNS + ch]; ss += v*v;
        }
        ss += __shfl_xor_sync(0xffffffffu, ss, 1);
        ss += __shfl_xor_sync(0xffffffffu, ss, 2);
        if (sub == 0) rstd_s[row] = rsqrtf(ss*(1.f/HIDDEN) + EPSV);
    }
    __syncthreads();

    for (int i = t; i < NN*APX*HIDDEN; i += 256) {
        int row = i >> 8, ch = i & 255;
        cn[row*CNS + ch] *= rstd_s[row] * rw_s[ch];
    }
    __syncthreads();

    {
        int p2 = t >> 2, sub = t & 3, lane = t & 31;
        int w = p2 >> 3, n = p2 & 7;
        const float* crow = &cn[(n*APX + w)*CNS];
        float pd[NHEADS];
        #pragma unroll
        for (int e = 0; e < NHEADS; e++) pd[e] = 0.f;
        #pragma unroll 4
        for (int j = 0; j < 64; j++) {
            int ch = sub*64 + ((j + lane) & 63);
            float cv = crow[ch];
            #pragma unroll
            for (int e = 0; e < NHEADS; e++) pd[e] += cv * kq_s[e*HIDDEN + ch];
        }
        #pragma unroll
        for (int e = 0; e < NHEADS; e++) {
            pd[e] += __shfl_xor_sync(0xffffffffu, pd[e], 1);
            pd[e] += __shfl_xor_sync(0xffffffffu, pd[e], 2);
        }
        if (sub == 0) {
            #pragma unroll
            for (int e = 0; e < NHEADS; e++) dots_s[(w*NHEADS + e)*NN + n] = pd[e];
        }
    }
    __syncthreads();

    if (t < APX*NHEADS) {
        float m = -1e30f;
        #pragma unroll
        for (int n = 0; n < NN; n++) m = fmaxf(m, dots_s[t*NN + n]);
        float ex[NN]; float s = 0.f;
        #pragma unroll
        for (int n = 0; n < NN; n++) { ex[n] = expf(dots_s[t*NN + n] - m); s += ex[n]; }
        float inv = 1.f/s;
        #pragma unroll
        for (int n = 0; n < NN; n++) attn_s[t*NN + n] = ex[n]*inv;
    }
    __syncthreads();

    int px_base = b*(HH*WW) + h*WW + w0;
    for (int w = 0; w < APX; w++) {
        float cv[NN];
        #pragma unroll
        for (int n = 0; n < NN; n++) cv[n] = cn[(n*APX + w)*CNS + t];
        #pragma unroll
        for (int e = 0; e < NHEADS; e++) {
            float acc = 0.f;
            #pragma unroll
            for (int n = 0; n < NN; n++) acc += attn_s[(w*NHEADS + e)*NN + n] * cv[n];
            g_cbar[(size_t)(px_base + w)*(NHEADS*HIDDEN) + e*HIDDEN + t] = acc;
        }
    }
}

// ---------------------------------------------------------------------------
// Kernel B (TF32 tensor cores): per 64-px tile, per head:
//   h_e[64,64] = cbar_e[64,256] @ Wv_e[256,64]   then   out[64,256] += h_e @ Wo_e[64,256]
// 256 threads = 8 warps as 4(M) x 2(N). mma.sync.m16n8k8.tf32.
// Strides 68/132 (== 4 mod 32) -> all fragment LDS bank-conflict-free.
// ---------------------------------------------------------------------------
#define BPX 64
#define AS_STRIDE 68
#define WO_STRIDE 132
// a_s [64][68] (u32 tf32) at 0; wv_s [64][68] at 4352; wo_s [64][132] aliases 0..8448
// h_s [64][68] at 8704; b_s [256] f32 at 13056. Total 13312 u32 = 53248 B.
#define SMEM_O_U32  13312
#define SMEM_O_BYTES (SMEM_O_U32*4)

__device__ __forceinline__ uint32_t f2tf(float x) {
    uint32_t r;
    asm("cvt.rna.tf32.f32 %0, %1;" : "=r"(r) : "f"(x));
    return r;
}

__device__ __forceinline__ void mma_tf32(float* c, const uint32_t* a, const uint32_t* b) {
    asm volatile("mma.sync.aligned.m16n8k8.row.col.f32.tf32.tf32.f32 "
                 "{%0,%1,%2,%3}, {%4,%5,%6,%7}, {%8,%9}, {%0,%1,%2,%3};"
                 : "+f"(c[0]), "+f"(c[1]), "+f"(c[2]), "+f"(c[3])
                 : "r"(a[0]), "r"(a[1]), "r"(a[2]), "r"(a[3]), "r"(b[0]), "r"(b[1]));
}

__global__ __launch_bounds__(256, 1)
void out_kernel(const float* __restrict__ w_kv, const float* __restrict__ w_out,
                const float* __restrict__ b_out, float* __restrict__ out)
{
    extern __shared__ uint32_t smo[];
    uint32_t* a_s  = smo;            // [64][68]  cbar k-chunk (tf32 bits)
    uint32_t* wv_s = smo + 4352;     // [64][68]  Wv k-chunk
    uint32_t* wo_s = smo;            // [64][132] aliases a_s+wv_s (8448 <= 8704)
    uint32_t* h_s  = smo + 8704;     // [64][68]  h tile (tf32 bits)
    float*    b_s  = (float*)(smo + 13056);  // [256]

    int t    = threadIdx.x;
    int warp = t >> 5, lane = t & 31;
    int wm   = warp >> 1, wn = warp & 1;     // 4 x 2 warp grid
    int gid  = lane >> 2, tig = lane & 3;    // mma groupID / threadID-in-group
    int p0   = blockIdx.x * BPX;

    if (t < HIDDEN) b_s[t] = b_out[t];

    // out accumulators: [cc 0..1][nt 0..7][4 regs] -> warp covers M16 x (2*64) ch
    float oacc[2][8][4];
    #pragma unroll
    for (int cc = 0; cc < 2; cc++)
        #pragma unroll
        for (int nt = 0; nt < 8; nt++)
            #pragma unroll
            for (int r = 0; r < 4; r++) oacc[cc][nt][r] = 0.f;

    for (int e = 0; e < NHEADS; e++) {
        // ---- GEMM1: h[64,64] = cbar_e[64,256] @ Wv_e[256,64] ----
        float c1[4][4];
        #pragma unroll
        for (int nt = 0; nt < 4; nt++)
            #pragma unroll
            for (int r = 0; r < 4; r++) c1[nt][r] = 0.f;

        for (int kc = 0; kc < 4; kc++) {
            for (int i = t; i < 4096; i += 256) {
                int px = i >> 6, k = i & 63;
                a_s[px*AS_STRIDE + k] =
                    f2tf(g_cbar[(size_t)(p0 + px)*(NHEADS*HIDDEN) + e*HIDDEN + kc*64 + k]);
            }
            for (int i = t; i < 4096; i += 256) {
                int k = i >> 6, d = i & 63;
                wv_s[k*AS_STRIDE + d] =
                    f2tf(w_kv[(size_t)(kc*64 + k)*(2*HS) + e*128 + 64 + d]);  // V half
            }
            __syncthreads();
            #pragma unroll
            for (int ks = 0; ks < 8; ks++) {
                uint32_t af[4];
                int ar = wm*16 + gid, ak = ks*8 + tig;
                af[0] = a_s[ar*AS_STRIDE + ak];
                af[1] = a_s[(ar+8)*AS_STRIDE + ak];
                af[2] = a_s[ar*AS_STRIDE + ak + 4];
                af[3] = a_s[(ar+8)*AS_STRIDE + ak + 4];
                #pragma unroll
                for (int nt = 0; nt < 4; nt++) {
                    uint32_t bf[2];
                    int bn = wn*32 + nt*8 + gid, bk = ks*8 + tig;
                    bf[0] = wv_s[bk*AS_STRIDE + bn];
                    bf[1] = wv_s[(bk+4)*AS_STRIDE + bn];
                    mma_tf32(c1[nt], af, bf);
                }
            }
            __syncthreads();
        }

        // write h tile (tf32 bits) — row = wm*16+gid(+8), col = wn*32+nt*8+2*tig(+1)
        #pragma unroll
        for (int nt = 0; nt < 4; nt++) {
            int col = wn*32 + nt*8 + 2*tig;
            int row = wm*16 + gid;
            h_s[row*AS_STRIDE + col]       = f2tf(c1[nt][0]);
            h_s[row*AS_STRIDE + col + 1]   = f2tf(c1[nt][1]);
            h_s[(row+8)*AS_STRIDE + col]   = f2tf(c1[nt][2]);
            h_s[(row+8)*AS_STRIDE + col+1] = f2tf(c1[nt][3]);
        }

        // ---- GEMM2: out[64,256] += h[64,64] @ Wo_e[64,256], 2 chunks of 128 ch ----
        for (int cc = 0; cc < 2; cc++) {
            for (int i = t; i < 8192; i += 256) {
                int k = i >> 7, ch = i & 127;
                wo_s[k*WO_STRIDE + ch] =
                    f2tf(w_out[(size_t)(e*64 + k)*HIDDEN + cc*128 + ch]);
            }
            __syncthreads();   // covers h_s writes (cc=0) and wo_s staging
            #pragma unroll
            for (int ks = 0; ks < 8; ks++) {
                uint32_t af[4];
                int ar = wm*16 + gid, ak = ks*8 + tig;
                af[0] = h_s[ar*AS_STRIDE + ak];
                af[1] = h_s[(ar+8)*AS_STRIDE + ak];
                af[2] = h_s[ar*AS_STRIDE + ak + 4];
                af[3] = h_s[(ar+8)*AS_STRIDE + ak + 4];
                #pragma unroll
                for (int nt = 0; nt < 8; nt++) {
                    uint32_t bf[2];
                    int bn = wn*64 + nt*8 + gid, bk = ks*8 + tig;
                    bf[0] = wo_s[bk*WO_STRIDE + bn];
                    bf[1] = wo_s[(bk+4)*WO_STRIDE + bn];
                    mma_tf32(oacc[cc][nt], af, bf);
                }
            }
            __syncthreads();   // before restaging wo_s / next head's a_s
        }
    }

    // bias + transposed store: out[b, ch, h, w]
    // px = p0 + wm*16 + gid (+8); ch = cc*128 + wn*64 + nt*8 + 2*tig (+1)
    #pragma unroll
    for (int cc = 0; cc < 2; cc++) {
        #pragma unroll
        for (int nt = 0; nt < 8; nt++) {
            int ch0 = cc*128 + wn*64 + nt*8 + 2*tig;
            float bi0 = b_s[ch0], bi1 = b_s[ch0+1];
            #pragma unroll
            for (int half = 0; half < 2; half++) {
                int px = p0 + wm*16 + gid + half*8;
                int bb = px >> 10, hh = (px >> 5) & 31, ww = px & 31;
                size_t base = (((size_t)bb*HIDDEN)*HH + hh)*WW + ww;
                out[base + (size_t)ch0    *HH*WW] = oacc[cc][nt][half*2+0] + bi0;
                out[base + (size_t)(ch0+1)*HH*WW] = oacc[cc][nt][half*2+1] + bi1;
            }
        }
    }
}

// ---------------------------------------------------------------------------
extern "C" void kernel_launch(void* const* d_in, const int* in_sizes, int n_in,
                              void* d_out, int out_size)
{
    const int*   q     = (const int*)  d_in[0];
    const float* c     = (const float*)d_in[1];
    const float* rms_w = (const float*)d_in[2];
    const float* emb   = (const float*)d_in[3];
    const float* w1    = (const float*)d_in[4];
    const float* b1    = (const float*)d_in[5];
    const float* w2    = (const float*)d_in[6];
    const float* b2    = (const float*)d_in[7];
    const float* w_kv  = (const float*)d_in[8];
    const float* w_out = (const float*)d_in[9];
    const float* b_out = (const float*)d_in[10];
    float* out = (float*)d_out;

    static int smem_set = 0;
    if (!smem_set) {
        cudaFuncSetAttribute(attn_kernel, cudaFuncAttributeMaxDynamicSharedMemorySize,
                             SMEM_A_BYTES);
        cudaFuncSetAttribute(out_kernel, cudaFuncAttributeMaxDynamicSharedMemorySize,
                             SMEM_O_BYTES);
        smem_set = 1;
    }

    q1_kernel<<<16, 256>>>(q, emb, w1, b1);
    q2_kernel<<<16, 256>>>(w2, b2);
    q3_kernel<<<64, 256>>>(w_kv);
    attn_kernel<<<NB*HH*(WW/APX), 256, SMEM_A_BYTES>>>(c, rms_w);
    out_kernel<<<NPIX/BPX, 256, SMEM_O_BYTES>>>(w_kv, w_out, b_out, out);
}

// round 6
// speedup vs baseline: 2.3151x; 1.4908x over previous
#include <cuda_runtime.h>
#include <math.h>
#include <stdint.h>

#define HIDDEN 256
#define HS     512
#define NHEADS 8
#define HDIM   64
#define NN     8        // tokens
#define NB     8        // batch
#define HH     32
#define WW     32
#define NPIX   (NB*HH*WW)   // 8192
#define EPSV   1e-6f
#define KTOT   (NHEADS*HIDDEN)   // 2048 fused K

// scratch (static __device__ — no allocation allowed)
__device__ float g_h1[NB*HS];
__device__ float g_qh[NB*HS];
__device__ float g_kq[NB*NHEADS*HIDDEN];
__device__ __align__(16) float    g_cbar[(size_t)NPIX*KTOT];  // [px][e*256+c], tf32 bits, 64MB
__device__ __align__(16) uint32_t g_M[(size_t)KTOT*HIDDEN];   // fused Wv@Wo, tf32 bits, 2MB

__device__ __forceinline__ uint32_t f2tf(float x) {
    uint32_t r;
    asm("cvt.rna.tf32.f32 %0, %1;" : "=r"(r) : "f"(x));
    return r;
}

__device__ __forceinline__ void mma_tf32(float* c, const uint32_t* a, const uint32_t* b) {
    asm volatile("mma.sync.aligned.m16n8k8.row.col.f32.tf32.tf32.f32 "
                 "{%0,%1,%2,%3}, {%4,%5,%6,%7}, {%8,%9}, {%0,%1,%2,%3};"
                 : "+f"(c[0]), "+f"(c[1]), "+f"(c[2]), "+f"(c[3])
                 : "r"(a[0]), "r"(a[1]), "r"(a[2]), "r"(a[3]), "r"(b[0]), "r"(b[1]));
}

__device__ __forceinline__ void cpa16(uint32_t dst, const void* src) {
    asm volatile("cp.async.cg.shared.global [%0], [%1], 16;" :: "r"(dst), "l"(src));
}

// ---------------------------------------------------------------------------
// Query path, stage 1: h1[b,j] = silu(emb[q[b]] @ w1 + b1)
// ---------------------------------------------------------------------------
__global__ void q1_kernel(const int* __restrict__ q, const float* __restrict__ emb,
                          const float* __restrict__ w1, const float* __restrict__ b1)
{
    __shared__ float qe[NB][HIDDEN];
    int t = threadIdx.x;
    for (int i = t; i < NB*HIDDEN; i += 256) {
        int b = i >> 8, cc = i & 255;
        qe[b][cc] = emb[(size_t)q[b]*HIDDEN + cc];
    }
    __syncthreads();
    int b = t >> 5, jl = t & 31;
    int j = blockIdx.x*32 + jl;
    float acc = b1[j];
    #pragma unroll 8
    for (int cc = 0; cc < HIDDEN; cc++) acc += qe[b][cc] * w1[(size_t)cc*HS + j];
    g_h1[b*HS + j] = acc / (1.f + expf(-acc));
}

// ---------------------------------------------------------------------------
// Query path, stage 2: qh[b,j] = h1[b] @ w2 + b2
// ---------------------------------------------------------------------------
__global__ void q2_kernel(const float* __restrict__ w2, const float* __restrict__ b2)
{
    __shared__ float h1s[NB][HS];
    int t = threadIdx.x;
    for (int i = t; i < NB*HS; i += 256) h1s[i >> 9][i & 511] = g_h1[i];
    __syncthreads();
    int b = t >> 5, jl = t & 31;
    int j = blockIdx.x*32 + jl;
    float acc = b2[j];
    #pragma unroll 8
    for (int i = 0; i < HS; i++) acc += h1s[b][i] * w2[(size_t)i*HS + j];
    g_qh[b*HS + j] = acc;
}

// ---------------------------------------------------------------------------
// Query path, stage 3: kq[b,e,c] = scale * (Wk_e^T qh_e)[c]
// ---------------------------------------------------------------------------
__global__ void q3_kernel(const float* __restrict__ w_kv)
{
    int b = blockIdx.x >> 3, e = blockIdx.x & 7;
    __shared__ float qhe[HDIM];
    int t = threadIdx.x;
    if (t < HDIM) qhe[t] = g_qh[b*HS + e*HDIM + t];
    __syncthreads();
    const float scale = rsqrtf((float)HDIM);
    const float4* wp = (const float4*)(w_kv + (size_t)t*(2*HS) + e*128);  // K half
    float acc = 0.f;
    #pragma unroll
    for (int d4 = 0; d4 < 16; d4++) {
        float4 v = wp[d4];
        acc += v.x*qhe[d4*4+0] + v.y*qhe[d4*4+1] + v.z*qhe[d4*4+2] + v.w*qhe[d4*4+3];
    }
    g_kq[b*NHEADS*HIDDEN + e*HIDDEN + t] = acc * scale;
}

// ---------------------------------------------------------------------------
// Kernel P: fused M[e*256+c, ch] = sum_d Wv_e[c,d] * Wo_e[d,ch], stored tf32.
// grid = 8 heads x 16 row-chunks = 128 blocks, 256 threads (one per ch).
// ---------------------------------------------------------------------------
__global__ void fuse_kernel(const float* __restrict__ w_kv, const float* __restrict__ w_out)
{
    __shared__ float wv_s[16*64];   // rows r0..r0+16 of Wv_e
    int e  = blockIdx.x >> 4;
    int r0 = (blockIdx.x & 15) * 16;
    int t  = threadIdx.x;

    for (int i = t; i < 16*64; i += 256) {
        int k = i >> 6, d = i & 63;
        wv_s[i] = w_kv[(size_t)(r0 + k)*(2*HS) + e*128 + 64 + d];   // V half
    }
    __syncthreads();

    float acc[16];
    #pragma unroll
    for (int k = 0; k < 16; k++) acc[k] = 0.f;
    #pragma unroll 4
    for (int d = 0; d < 64; d++) {
        float wo = w_out[(size_t)(e*64 + d)*HIDDEN + t];
        #pragma unroll
        for (int k = 0; k < 16; k++) acc[k] += wv_s[k*64 + d] * wo;
    }
    #pragma unroll
    for (int k = 0; k < 16; k++)
        g_M[(size_t)(e*HIDDEN + r0 + k)*HIDDEN + t] = f2tf(acc[k]);
}

// ---------------------------------------------------------------------------
// Kernel A: per-pixel RMSNorm + dots + softmax + cbar (writes tf32-rounded bits)
// ---------------------------------------------------------------------------
#define APX 8
#define CNS 260
#define SMEM_A_FLOATS (NN*APX*CNS + NHEADS*HIDDEN + HIDDEN + NN*APX + 2*APX*NHEADS*NN)
#define SMEM_A_BYTES  (SMEM_A_FLOATS*4)

__global__ __launch_bounds__(256)
void attn_kernel(const float* __restrict__ c, const float* __restrict__ rms_w)
{
    extern __shared__ float sma[];
    float* cn     = sma;
    float* kq_s   = cn + NN*APX*CNS;
    float* rw_s   = kq_s + NHEADS*HIDDEN;
    float* rstd_s = rw_s + HIDDEN;
    float* dots_s = rstd_s + NN*APX;
    float* attn_s = dots_s + APX*NHEADS*NN;

    int t = threadIdx.x;
    int blk = blockIdx.x;
    int b  = blk >> 7;
    int h  = (blk >> 2) & 31;
    int w0 = (blk & 3) * APX;

    for (int i = t; i < NHEADS*HIDDEN; i += 256) kq_s[i] = g_kq[b*NHEADS*HIDDEN + i];
    if (t < HIDDEN) rw_s[t] = rms_w[t];

    const float* cb = c + ((size_t)b*NN)*HIDDEN*(HH*WW) + h*WW + w0;
    int wl = t & 7, chb = t >> 3;
    for (int n = 0; n < NN; n++) {
        #pragma unroll
        for (int cp = 0; cp < 8; cp++) {
            int ch = cp*32 + chb;
            cn[(n*APX + wl)*CNS + ch] = cb[((size_t)n*HIDDEN + ch)*(HH*WW) + wl];
        }
    }
    __syncthreads();

    {
        int row = t >> 2, sub = t & 3;
        float ss = 0.f;
        for (int ch = sub; ch < HIDDEN; ch += 4) {
            float v = cn[row*CNS + ch]; ss += v*v;
        }
        ss += __shfl_xor_sync(0xffffffffu, ss, 1);
        ss += __shfl_xor_sync(0xffffffffu, ss, 2);
        if (sub == 0) rstd_s[row] = rsqrtf(ss*(1.f/HIDDEN) + EPSV);
    }
    __syncthreads();

    for (int i = t; i < NN*APX*HIDDEN; i += 256) {
        int row = i >> 8, ch = i & 255;
        cn[row*CNS + ch] *= rstd_s[row] * rw_s[ch];
    }
    __syncthreads();

    {
        int p2 = t >> 2, sub = t & 3, lane = t & 31;
        int w = p2 >> 3, n = p2 & 7;
        const float* crow = &cn[(n*APX + w)*CNS];
        float pd[NHEADS];
        #pragma unroll
        for (int e = 0; e < NHEADS; e++) pd[e] = 0.f;
        #pragma unroll 4
        for (int j = 0; j < 64; j++) {
            int ch = sub*64 + ((j + lane) & 63);
            float cv = crow[ch];
            #pragma unroll
            for (int e = 0; e < NHEADS; e++) pd[e] += cv * kq_s[e*HIDDEN + ch];
        }
        #pragma unroll
        for (int e = 0; e < NHEADS; e++) {
            pd[e] += __shfl_xor_sync(0xffffffffu, pd[e], 1);
            pd[e] += __shfl_xor_sync(0xffffffffu, pd[e], 2);
        }
        if (sub == 0) {
            #pragma unroll
            for (int e = 0; e < NHEADS; e++) dots_s[(w*NHEADS + e)*NN + n] = pd[e];
        }
    }
    __syncthreads();

    if (t < APX*NHEADS) {
        float m = -1e30f;
        #pragma unroll
        for (int n = 0; n < NN; n++) m = fmaxf(m, dots_s[t*NN + n]);
        float ex[NN]; float s = 0.f;
        #pragma unroll
        for (int n = 0; n < NN; n++) { ex[n] = expf(dots_s[t*NN + n] - m); s += ex[n]; }
        float inv = 1.f/s;
        #pragma unroll
        for (int n = 0; n < NN; n++) attn_s[t*NN + n] = ex[n]*inv;
    }
    __syncthreads();

    int px_base = b*(HH*WW) + h*WW + w0;
    for (int w = 0; w < APX; w++) {
        float cv[NN];
        #pragma unroll
        for (int n = 0; n < NN; n++) cv[n] = cn[(n*APX + w)*CNS + t];
        #pragma unroll
        for (int e = 0; e < NHEADS; e++) {
            float acc = 0.f;
            #pragma unroll
            for (int n = 0; n < NN; n++) acc += attn_s[(w*NHEADS + e)*NN + n] * cv[n];
            // store pre-rounded tf32 bits (consumed raw by the fused GEMM)
            ((uint32_t*)g_cbar)[(size_t)(px_base + w)*KTOT + e*HIDDEN + t] = f2tf(acc);
        }
    }
}

// ---------------------------------------------------------------------------
// Kernel G: out[8192,256] = cbar[8192,2048] @ M[2048,256] + b  (tf32 mma)
// 128 blocks x 64-px tiles; 8 warps = 2(M:32px) x 4(N:64ch); K in 64 chunks of
// 32, cp.async double-buffered. No conversions in the loop (inputs pre-tf32).
// ---------------------------------------------------------------------------
#define BPX 64
#define KC  32
#define SA  36                     // A row stride (floats): banks 4*px+tig, conflict-free
#define SB  260                    // B row stride: banks 4*k+ch, conflict-free
#define STG_U32 (BPX*SA + KC*SB)   // 2304 + 8320 = 10624 per stage
#define SMEM_G_BYTES ((2*STG_U32 + HIDDEN)*4)   // 86016

__global__ __launch_bounds__(256, 1)
void gemm_kernel(const float* __restrict__ b_out, float* __restrict__ out)
{
    extern __shared__ uint32_t smg[];
    float* b_s = (float*)(smg + 2*STG_U32);

    int t    = threadIdx.x;
    int warp = t >> 5, lane = t & 31;
    int wm   = warp >> 2, wn = warp & 3;     // 2 x 4 warp grid
    int gid  = lane >> 2, tig = lane & 3;
    int p0   = blockIdx.x * BPX;

    uint32_t smem_base;
    {
        uint32_t a;
        asm("{ .reg .u64 tmp; cvta.to.shared.u64 tmp, %1; cvt.u32.u64 %0, tmp; }"
            : "=r"(a) : "l"(smg));
        smem_base = a;
    }

    if (t < HIDDEN) b_s[t] = b_out[t];

    float acc[2][8][4];
    #pragma unroll
    for (int mt = 0; mt < 2; mt++)
        #pragma unroll
        for (int nt = 0; nt < 8; nt++)
            #pragma unroll
            for (int r = 0; r < 4; r++) acc[mt][nt][r] = 0.f;

    const uint32_t* cb = (const uint32_t*)g_cbar;

    // ---- stage chunk 0 into buffer 0 ----
    {
        uint32_t ab = smem_base;
        uint32_t bb = ab + BPX*SA*4;
        #pragma unroll
        for (int r = 0; r < 2; r++) {
            int i = t + r*256;                 // 512 A units
            int px = i >> 3, kg = i & 7;
            cpa16(ab + (px*SA + kg*4)*4, cb + (size_t)(p0+px)*KTOT + kg*4);
        }
        #pragma unroll
        for (int r = 0; r < 8; r++) {
            int i = t + r*256;                 // 2048 B units
            int k = i >> 6, cg = i & 63;
            cpa16(bb + (k*SB + cg*4)*4, g_M + (size_t)k*HIDDEN + cg*4);
        }
        asm volatile("cp.async.commit_group;");
    }

    const int NCH = KTOT/KC;   // 64
    for (int kc = 0; kc < NCH; kc++) {
        if (kc + 1 < NCH) {
            uint32_t ab = smem_base + ((kc+1)&1)*STG_U32*4;
            uint32_t bb = ab + BPX*SA*4;
            int koff = (kc+1)*KC;
            #pragma unroll
            for (int r = 0; r < 2; r++) {
                int i = t + r*256;
                int px = i >> 3, kg = i & 7;
                cpa16(ab + (px*SA + kg*4)*4, cb + (size_t)(p0+px)*KTOT + koff + kg*4);
            }
            #pragma unroll
            for (int r = 0; r < 8; r++) {
                int i = t + r*256;
                int k = i >> 6, cg = i & 63;
                cpa16(bb + (k*SB + cg*4)*4, g_M + (size_t)(koff + k)*HIDDEN + cg*4);
            }
            asm volatile("cp.async.commit_group;");
            asm volatile("cp.async.wait_group 1;");
        } else {
            asm volatile("cp.async.wait_group 0;");
        }
        __syncthreads();

        const uint32_t* a_p = smg + (kc&1)*STG_U32;
        const uint32_t* b_p = a_p + BPX*SA;

        #pragma unroll
        for (int ks = 0; ks < 4; ks++) {
            uint32_t af[2][4];
            #pragma unroll
            for (int mt = 0; mt < 2; mt++) {
                int ar = wm*32 + mt*16 + gid, ak = ks*8 + tig;
                af[mt][0] = a_p[ar*SA + ak];
                af[mt][1] = a_p[(ar+8)*SA + ak];
                af[mt][2] = a_p[ar*SA + ak + 4];
                af[mt][3] = a_p[(ar+8)*SA + ak + 4];
            }
            #pragma unroll
            for (int nt = 0; nt < 8; nt++) {
                uint32_t bf[2];
                int bn = wn*64 + nt*8 + gid, bk = ks*8 + tig;
                bf[0] = b_p[bk*SB + bn];
                bf[1] = b_p[(bk+4)*SB + bn];
                mma_tf32(acc[0][nt], af[0], bf);
                mma_tf32(acc[1][nt], af[1], bf);
            }
        }
        __syncthreads();
    }

    // bias + transposed store: out[b, ch, h, w]
    #pragma unroll
    for (int mt = 0; mt < 2; mt++) {
        #pragma unroll
        for (int nt = 0; nt < 8; nt++) {
            int ch0 = wn*64 + nt*8 + 2*tig;
            float bi0 = b_s[ch0], bi1 = b_s[ch0+1];
            #pragma unroll
            for (int half = 0; half < 2; half++) {
                int px = p0 + wm*32 + mt*16 + half*8 + gid;
                int bb = px >> 10, hh = (px >> 5) & 31, ww = px & 31;
                size_t base = (((size_t)bb*HIDDEN)*HH + hh)*WW + ww;
                out[base + (size_t)ch0    *HH*WW] = acc[mt][nt][half*2+0] + bi0;
                out[base + (size_t)(ch0+1)*HH*WW] = acc[mt][nt][half*2+1] + bi1;
            }
        }
    }
}

// ---------------------------------------------------------------------------
extern "C" void kernel_launch(void* const* d_in, const int* in_sizes, int n_in,
                              void* d_out, int out_size)
{
    const int*   q     = (const int*)  d_in[0];
    const float* c     = (const float*)d_in[1];
    const float* rms_w = (const float*)d_in[2];
    const float* emb   = (const float*)d_in[3];
    const float* w1    = (const float*)d_in[4];
    const float* b1    = (const float*)d_in[5];
    const float* w2    = (const float*)d_in[6];
    const float* b2    = (const float*)d_in[7];
    const float* w_kv  = (const float*)d_in[8];
    const float* w_out = (const float*)d_in[9];
    const float* b_out = (const float*)d_in[10];
    float* out = (float*)d_out;

    // unconditional (no static guards; not a stream op, capture-safe)
    cudaFuncSetAttribute(attn_kernel, cudaFuncAttributeMaxDynamicSharedMemorySize,
                         SMEM_A_BYTES);
    cudaFuncSetAttribute(gemm_kernel, cudaFuncAttributeMaxDynamicSharedMemorySize,
                         SMEM_G_BYTES);

    q1_kernel<<<16, 256>>>(q, emb, w1, b1);
    q2_kernel<<<16, 256>>>(w2, b2);
    q3_kernel<<<64, 256>>>(w_kv);
    fuse_kernel<<<128, 256>>>(w_kv, w_out);
    attn_kernel<<<NB*HH*(WW/APX), 256, SMEM_A_BYTES>>>(c, rms_w);
    gemm_kernel<<<NPIX/BPX, 256, SMEM_G_BYTES>>>(b_out, out);
}

// round 11
// speedup vs baseline: 2.6192x; 1.1314x over previous
#include <cuda_runtime.h>
#include <math.h>
#include <stdint.h>

#define HIDDEN 256
#define HS     512
#define NHEADS 8
#define HDIM   64
#define NN     8        // tokens
#define NB     8        // batch
#define HH     32
#define WW     32
#define NPIX   (NB*HH*WW)   // 8192
#define EPSV   1e-6f
#define KTOT   (NHEADS*HIDDEN)   // 2048 fused K

// scratch (static __device__ — no allocation allowed)
__device__ float g_h1[NB*HS];
__device__ float g_qh[NB*HS];
__device__ float g_kq[NB*NHEADS*HIDDEN];
__device__ __align__(16) float    g_cbar[(size_t)NPIX*KTOT];  // [px][e*256+c], tf32 bits, 64MB
__device__ __align__(16) uint32_t g_M[(size_t)KTOT*HIDDEN];   // fused Wv@Wo, FRAGMENT-major tf32

__device__ __forceinline__ uint32_t f2tf(float x) {
    uint32_t r;
    asm("cvt.rna.tf32.f32 %0, %1;" : "=r"(r) : "f"(x));
    return r;
}

__device__ __forceinline__ void mma_tf32(float* c, const uint32_t* a, const uint32_t* b) {
    asm volatile("mma.sync.aligned.m16n8k8.row.col.f32.tf32.tf32.f32 "
                 "{%0,%1,%2,%3}, {%4,%5,%6,%7}, {%8,%9}, {%0,%1,%2,%3};"
                 : "+f"(c[0]), "+f"(c[1]), "+f"(c[2]), "+f"(c[3])
                 : "r"(a[0]), "r"(a[1]), "r"(a[2]), "r"(a[3]), "r"(b[0]), "r"(b[1]));
}

__device__ __forceinline__ void cpa16(uint32_t dst, const void* src) {
    asm volatile("cp.async.cg.shared.global [%0], [%1], 16;" :: "r"(dst), "l"(src));
}

// ---------------------------------------------------------------------------
// Query path, stage 1: h1[b,j] = silu(emb[q[b]] @ w1 + b1)
// ---------------------------------------------------------------------------
__global__ void q1_kernel(const int* __restrict__ q, const float* __restrict__ emb,
                          const float* __restrict__ w1, const float* __restrict__ b1)
{
    __shared__ float qe[NB][HIDDEN];
    int t = threadIdx.x;
    for (int i = t; i < NB*HIDDEN; i += 256) {
        int b = i >> 8, cc = i & 255;
        qe[b][cc] = emb[(size_t)q[b]*HIDDEN + cc];
    }
    __syncthreads();
    int b = t >> 5, jl = t & 31;
    int j = blockIdx.x*32 + jl;
    float acc = b1[j];
    #pragma unroll 8
    for (int cc = 0; cc < HIDDEN; cc++) acc += qe[b][cc] * w1[(size_t)cc*HS + j];
    g_h1[b*HS + j] = acc / (1.f + expf(-acc));
}

// ---------------------------------------------------------------------------
// Query path, stage 2: qh[b,j] = h1[b] @ w2 + b2
// ---------------------------------------------------------------------------
__global__ void q2_kernel(const float* __restrict__ w2, const float* __restrict__ b2)
{
    __shared__ float h1s[NB][HS];
    int t = threadIdx.x;
    for (int i = t; i < NB*HS; i += 256) h1s[i >> 9][i & 511] = g_h1[i];
    __syncthreads();
    int b = t >> 5, jl = t & 31;
    int j = blockIdx.x*32 + jl;
    float acc = b2[j];
    #pragma unroll 8
    for (int i = 0; i < HS; i++) acc += h1s[b][i] * w2[(size_t)i*HS + j];
    g_qh[b*HS + j] = acc;
}

// ---------------------------------------------------------------------------
// Query path, stage 3: kq[b,e,c] = scale * (Wk_e^T qh_e)[c]
// ---------------------------------------------------------------------------
__global__ void q3_kernel(const float* __restrict__ w_kv)
{
    int b = blockIdx.x >> 3, e = blockIdx.x & 7;
    __shared__ float qhe[HDIM];
    int t = threadIdx.x;
    if (t < HDIM) qhe[t] = g_qh[b*HS + e*HDIM + t];
    __syncthreads();
    const float scale = rsqrtf((float)HDIM);
    const float4* wp = (const float4*)(w_kv + (size_t)t*(2*HS) + e*128);  // K half
    float acc = 0.f;
    #pragma unroll
    for (int d4 = 0; d4 < 16; d4++) {
        float4 v = wp[d4];
        acc += v.x*qhe[d4*4+0] + v.y*qhe[d4*4+1] + v.z*qhe[d4*4+2] + v.w*qhe[d4*4+3];
    }
    g_kq[b*NHEADS*HIDDEN + e*HIDDEN + t] = acc * scale;
}

// ---------------------------------------------------------------------------
// Kernel P: M[e*256+r, ch] = sum_d Wv_e[r,d] * Wo_e[d,ch], written in the mma
// B-fragment-major layout consumed by gemm_kernel:
//   k -> kc=k>>5, ks=(k>>3)&3, tig=k&3, half=(k>>2)&1 ; ch -> chb=ch>>3, gid=ch&7
//   u32 off = ((kc*4+ks)*32 + chb)*64 + (gid*4+tig)*2 + half
// grid = 8 heads x 16 row-chunks = 128 blocks, 256 threads. Wo_e staged in smem.
// ---------------------------------------------------------------------------
#define SMEM_P_BYTES ((16*64 + 64*HIDDEN)*4)   // wv 4KB + wo 64KB = 69632

__global__ void fuse_kernel(const float* __restrict__ w_kv, const float* __restrict__ w_out)
{
    extern __shared__ float smp[];
    float* wv_s = smp;            // [16][64]
    float* wo_s = smp + 16*64;    // [64][256]

    int e  = blockIdx.x >> 4;
    int r0 = (blockIdx.x & 15) * 16;
    int t  = threadIdx.x;

    for (int i = t; i < 16*64; i += 256) {
        int k = i >> 6, d = i & 63;
        wv_s[i] = w_kv[(size_t)(r0 + k)*(2*HS) + e*128 + 64 + d];   // V half
    }
    // stage Wo_e [64][256] coalesced (float4)
    {
        const float4* src = (const float4*)(w_out + (size_t)e*64*HIDDEN);
        float4* dst = (float4*)wo_s;
        #pragma unroll
        for (int r = 0; r < 16; r++) dst[t + r*256] = src[t + r*256];
    }
    __syncthreads();

    float acc[16];
    #pragma unroll
    for (int k = 0; k < 16; k++) acc[k] = 0.f;
    #pragma unroll 8
    for (int d = 0; d < 64; d++) {
        float wo = wo_s[d*HIDDEN + t];
        #pragma unroll
        for (int k = 0; k < 16; k++) acc[k] += wv_s[k*64 + d] * wo;
    }

    int chb = t >> 3, gid = t & 7;
    #pragma unroll
    for (int kk = 0; kk < 16; kk++) {
        int k = e*HIDDEN + r0 + kk;
        int kc = k >> 5, ks = (k >> 3) & 3, tig = k & 3, half = (k >> 2) & 1;
        g_M[(size_t)((kc*4 + ks)*32 + chb)*64 + (gid*4 + tig)*2 + half] = f2tf(acc[kk]);
    }
}

// ---------------------------------------------------------------------------
// Kernel A: per-pixel RMSNorm + dots + softmax + cbar (writes tf32-rounded bits)
// ---------------------------------------------------------------------------
#define APX 8
#define CNS 260
#define SMEM_A_FLOATS (NN*APX*CNS + NHEADS*HIDDEN + HIDDEN + NN*APX + 2*APX*NHEADS*NN)
#define SMEM_A_BYTES  (SMEM_A_FLOATS*4)

__global__ __launch_bounds__(256)
void attn_kernel(const float* __restrict__ c, const float* __restrict__ rms_w)
{
    extern __shared__ float sma[];
    float* cn     = sma;
    float* kq_s   = cn + NN*APX*CNS;
    float* rw_s   = kq_s + NHEADS*HIDDEN;
    float* rstd_s = rw_s + HIDDEN;
    float* dots_s = rstd_s + NN*APX;
    float* attn_s = dots_s + APX*NHEADS*NN;

    int t = threadIdx.x;
    int blk = blockIdx.x;
    int b  = blk >> 7;
    int h  = (blk >> 2) & 31;
    int w0 = (blk & 3) * APX;

    for (int i = t; i < NHEADS*HIDDEN; i += 256) kq_s[i] = g_kq[b*NHEADS*HIDDEN + i];
    if (t < HIDDEN) rw_s[t] = rms_w[t];

    const float* cb = c + ((size_t)b*NN)*HIDDEN*(HH*WW) + h*WW + w0;
    int wl = t & 7, chb = t >> 3;
    for (int n = 0; n < NN; n++) {
        #pragma unroll
        for (int cp = 0; cp < 8; cp++) {
            int ch = cp*32 + chb;
            cn[(n*APX + wl)*CNS + ch] = cb[((size_t)n*HIDDEN + ch)*(HH*WW) + wl];
        }
    }
    __syncthreads();

    {
        int row = t >> 2, sub = t & 3;
        float ss = 0.f;
        for (int ch = sub; ch < HIDDEN; ch += 4) {
            float v = cn[row*CNS + ch]; ss += v*v;
        }
        ss += __shfl_xor_sync(0xffffffffu, ss, 1);
        ss += __shfl_xor_sync(0xffffffffu, ss, 2);
        if (sub == 0) rstd_s[row] = rsqrtf(ss*(1.f/HIDDEN) + EPSV);
    }
    __syncthreads();

    for (int i = t; i < NN*APX*HIDDEN; i += 256) {
        int row = i >> 8, ch = i & 255;
        cn[row*CNS + ch] *= rstd_s[row] * rw_s[ch];
    }
    __syncthreads();

    {
        int p2 = t >> 2, sub = t & 3, lane = t & 31;
        int w = p2 >> 3, n = p2 & 7;
        const float* crow = &cn[(n*APX + w)*CNS];
        float pd[NHEADS];
        #pragma unroll
        for (int e = 0; e < NHEADS; e++) pd[e] = 0.f;
        #pragma unroll 4
        for (int j = 0; j < 64; j++) {
            int ch = sub*64 + ((j + lane) & 63);
            float cv = crow[ch];
            #pragma unroll
            for (int e = 0; e < NHEADS; e++) pd[e] += cv * kq_s[e*HIDDEN + ch];
        }
        #pragma unroll
        for (int e = 0; e < NHEADS; e++) {
            pd[e] += __shfl_xor_sync(0xffffffffu, pd[e], 1);
            pd[e] += __shfl_xor_sync(0xffffffffu, pd[e], 2);
        }
        if (sub == 0) {
            #pragma unroll
            for (int e = 0; e < NHEADS; e++) dots_s[(w*NHEADS + e)*NN + n] = pd[e];
        }
    }
    __syncthreads();

    if (t < APX*NHEADS) {
        float m = -1e30f;
        #pragma unroll
        for (int n = 0; n < NN; n++) m = fmaxf(m, dots_s[t*NN + n]);
        float ex[NN]; float s = 0.f;
        #pragma unroll
        for (int n = 0; n < NN; n++) { ex[n] = expf(dots_s[t*NN + n] - m); s += ex[n]; }
        float inv = 1.f/s;
        #pragma unroll
        for (int n = 0; n < NN; n++) attn_s[t*NN + n] = ex[n]*inv;
    }
    __syncthreads();

    int px_base = b*(HH*WW) + h*WW + w0;
    for (int w = 0; w < APX; w++) {
        float cv[NN];
        #pragma unroll
        for (int n = 0; n < NN; n++) cv[n] = cn[(n*APX + w)*CNS + t];
        #pragma unroll
        for (int e = 0; e < NHEADS; e++) {
            float acc = 0.f;
            #pragma unroll
            for (int n = 0; n < NN; n++) acc += attn_s[(w*NHEADS + e)*NN + n] * cv[n];
            ((uint32_t*)g_cbar)[(size_t)(px_base + w)*KTOT + e*HIDDEN + t] = f2tf(acc);
        }
    }
}

// ---------------------------------------------------------------------------
// Kernel G: out[8192,256] = cbar[8192,2048] @ M[2048,256] + b  (tf32 mma)
// 128 blocks x 64-px tiles; 8 warps = 2(M) x 4(N); KC=32, 4-stage cp.async
// pipeline, ONE barrier per chunk, B fragment-major (LDS.64, conflict-free).
// ---------------------------------------------------------------------------
#define BPX 64
#define KC  32
#define SA  36                        // A row stride (u32)
#define B_U32 (KC*HIDDEN)             // 8192 u32 per chunk, fragment-major
#define STG_U32 (BPX*SA + B_U32)      // 2304 + 8192 = 10496
#define NSTG 4
#define SMEM_G_BYTES ((NSTG*STG_U32 + HIDDEN)*4)   // 168960

// stage one K-chunk into pipeline slot (all 256 threads participate)
__device__ __forceinline__ void g_stage(uint32_t smem_base, int t, int p0,
                                        const uint32_t* cb, int kc, int slot)
{
    uint32_t ab = smem_base + slot*STG_U32*4;
    uint32_t bb = ab + BPX*SA*4;
    int koff = kc*KC;
    #pragma unroll
    for (int r = 0; r < 2; r++) {
        int i = t + r*256;                 // 512 A 16B-units
        int px = i >> 3, kg = i & 7;
        cpa16(ab + (px*SA + kg*4)*4, cb + (size_t)(p0+px)*KTOT + koff + kg*4);
    }
    const uint32_t* msrc = g_M + (size_t)kc*B_U32;   // fragment-major, contiguous
    #pragma unroll
    for (int r = 0; r < 8; r++) {
        int i = t + r*256;                 // 2048 B 16B-units
        cpa16(bb + i*16, msrc + i*4);
    }
}

__global__ __launch_bounds__(256, 1)
void gemm_kernel(const float* __restrict__ b_out, float* __restrict__ out)
{
    extern __shared__ uint32_t smg[];
    float* b_s = (float*)(smg + NSTG*STG_U32);

    int t    = threadIdx.x;
    int warp = t >> 5, lane = t & 31;
    int wm   = warp >> 2, wn = warp & 3;     // 2 x 4 warp grid
    int gid  = lane >> 2, tig = lane & 3;
    int p0   = blockIdx.x * BPX;

    uint32_t smem_base;
    {
        uint32_t a;
        asm("{ .reg .u64 tmp; cvta.to.shared.u64 tmp, %1; cvt.u32.u64 %0, tmp; }"
            : "=r"(a) : "l"(smg));
        smem_base = a;
    }

    if (t < HIDDEN) b_s[t] = b_out[t];

    float acc[2][8][4];
    #pragma unroll
    for (int mt = 0; mt < 2; mt++)
        #pragma unroll
        for (int nt = 0; nt < 8; nt++)
            #pragma unroll
            for (int r = 0; r < 4; r++) acc[mt][nt][r] = 0.f;

    const uint32_t* cb = (const uint32_t*)g_cbar;
    const int NCH = KTOT/KC;   // 64

    // prologue: stages 0..2
    #pragma unroll
    for (int s = 0; s < NSTG-1; s++) {
        g_stage(smem_base, t, p0, cb, s, s);
        asm volatile("cp.async.commit_group;");
    }

    for (int kc = 0; kc < NCH; kc++) {
        asm volatile("cp.async.wait_group %0;" :: "n"(NSTG-2));
        __syncthreads();

        // prefetch kc+3 into slot (kc+3)%4 (safe: all warps done with that slot)
        if (kc + NSTG-1 < NCH) g_stage(smem_base, t, p0, cb, kc + NSTG-1, (kc + NSTG-1) & (NSTG-1));
        asm volatile("cp.async.commit_group;");   // always commit (may be empty)

        const uint32_t* a_p = smg + (kc & (NSTG-1))*STG_U32;
        const uint2*    b_p = (const uint2*)(a_p + BPX*SA);

        #pragma unroll
        for (int ks = 0; ks < 4; ks++) {
            uint32_t af[2][4];
            #pragma unroll
            for (int mt = 0; mt < 2; mt++) {
                int ar = wm*32 + mt*16 + gid, ak = ks*8 + tig;
                af[mt][0] = a_p[ar*SA + ak];
                af[mt][1] = a_p[(ar+8)*SA + ak];
                af[mt][2] = a_p[ar*SA + ak + 4];
                af[mt][3] = a_p[(ar+8)*SA + ak + 4];
            }
            #pragma unroll
            for (int nt = 0; nt < 8; nt++) {
                uint2 bv = b_p[(ks*32 + wn*8 + nt)*32 + lane];
                uint32_t bf[2] = {bv.x, bv.y};
                mma_tf32(acc[0][nt], af[0], bf);
                mma_tf32(acc[1][nt], af[1], bf);
            }
        }
    }

    __syncthreads();   // all compute done before epilogue

    // bias + transposed store: out[b, ch, h, w]
    #pragma unroll
    for (int mt = 0; mt < 2; mt++) {
        #pragma unroll
        for (int nt = 0; nt < 8; nt++) {
            int ch0 = wn*64 + nt*8 + 2*tig;
            float bi0 = b_s[ch0], bi1 = b_s[ch0+1];
            #pragma unroll
            for (int half = 0; half < 2; half++) {
                int px = p0 + wm*32 + mt*16 + half*8 + gid;
                int bb = px >> 10, hh = (px >> 5) & 31, ww = px & 31;
                size_t base = (((size_t)bb*HIDDEN)*HH + hh)*WW + ww;
                out[base + (size_t)ch0    *HH*WW] = acc[mt][nt][half*2+0] + bi0;
                out[base + (size_t)(ch0+1)*HH*WW] = acc[mt][nt][half*2+1] + bi1;
            }
        }
    }
}

// ---------------------------------------------------------------------------
extern "C" void kernel_launch(void* const* d_in, const int* in_sizes, int n_in,
                              void* d_out, int out_size)
{
    const int*   q     = (const int*)  d_in[0];
    const float* c     = (const float*)d_in[1];
    const float* rms_w = (const float*)d_in[2];
    const float* emb   = (const float*)d_in[3];
    const float* w1    = (const float*)d_in[4];
    const float* b1    = (const float*)d_in[5];
    const float* w2    = (const float*)d_in[6];
    const float* b2    = (const float*)d_in[7];
    const float* w_kv  = (const float*)d_in[8];
    const float* w_out = (const float*)d_in[9];
    const float* b_out = (const float*)d_in[10];
    float* out = (float*)d_out;

    cudaFuncSetAttribute(attn_kernel, cudaFuncAttributeMaxDynamicSharedMemorySize,
                         SMEM_A_BYTES);
    cudaFuncSetAttribute(gemm_kernel, cudaFuncAttributeMaxDynamicSharedMemorySize,
                         SMEM_G_BYTES);
    cudaFuncSetAttribute(fuse_kernel, cudaFuncAttributeMaxDynamicSharedMemorySize,
                         SMEM_P_BYTES);

    q1_kernel<<<16, 256>>>(q, emb, w1, b1);
    q2_kernel<<<16, 256>>>(w2, b2);
    q3_kernel<<<64, 256>>>(w_kv);
    fuse_kernel<<<128, 256, SMEM_P_BYTES>>>(w_kv, w_out);
    attn_kernel<<<NB*HH*(WW/APX), 256, SMEM_A_BYTES>>>(c, rms_w);
    gemm_kernel<<<NPIX/BPX, 256, SMEM_G_BYTES>>>(b_out, out);
}